// round 2
// baseline (speedup 1.0000x reference)
#include <cuda_runtime.h>
#include <math.h>

// Problem constants (fixed shapes)
#define B_  4
#define H_  16
#define S_  8192
#define D_  64
#define M_  64
#define BH_ (B_*H_)
#define C_  (D_+1)          // 65: [V | ones]
#define TS  128             // rows per tile
#define NSPLIT 4
#define TILES_PER_SPLIT (S_/(TS*NSPLIT))   // 16

// Global scratch for buf1 = k'^T [V|1], per head: 64 x 65 fp32.
// Zeroed at the start of every kernel_launch -> deterministic under graph replay.
__device__ float g_buf1[BH_*M_*C_];

__global__ void zero_buf1_kernel() {
    int i = blockIdx.x*blockDim.x + threadIdx.x;
    if (i < BH_*M_*C_) g_buf1[i] = 0.0f;
}

// ---------------------------------------------------------------------------
// Phase K: compute k' = h(k) * exp(K . Omega) tilewise, accumulate
// buf1[m][c] += sum_s k'[s][m] * C[s][c]  (C = [V | 1])
// Grid: (64 heads, 4 S-splits). Each block loops over 16 tiles of 128 rows,
// keeps its partial buf1 in registers, atomicAdds once at the end.
// ---------------------------------------------------------------------------
__global__ void __launch_bounds__(256, 2)
phase_k_kernel(const float* __restrict__ Kg, const float* __restrict__ Vg,
               const float* __restrict__ Og)
{
    extern __shared__ float sm[];
    float* Om   = sm;                 // [64][64]   omega, d-major
    float* KC   = sm + 4096;          // [128][68]  K tile, then V|1 tile (reused)
    float* KP   = KC + TS*68;         // [128][68]  k' tile
    float* hrow = KP + TS*68;         // [128]

    const int t  = threadIdx.x;
    const int bh = blockIdx.x;
    const int sp = blockIdx.y;
    const int tx = t & 15;            // 0..15
    const int ty = t >> 4;            // 0..15

    // Load omega (64x64) once
    for (int i = t; i < (D_*M_)/4; i += 256)
        ((float4*)Om)[i] = ((const float4*)Og)[i];

    float acc2[4][4];
    float accD[4];
#pragma unroll
    for (int a = 0; a < 4; ++a) {
        accD[a] = 0.f;
#pragma unroll
        for (int b = 0; b < 4; ++b) acc2[a][b] = 0.f;
    }

    const size_t base = (size_t)bh*S_*D_ + (size_t)sp*TILES_PER_SPLIT*TS*D_;

    for (int tile = 0; tile < TILES_PER_SPLIT; ++tile) {
        const float* Kt = Kg + base + (size_t)tile*TS*D_;
        const float* Vt = Vg + base + (size_t)tile*TS*D_;

        __syncthreads();  // protect KC/KP from previous iteration's readers

        // Load K tile (128x64) into KC (stride 68)
        for (int i = t; i < TS*D_/4; i += 256) {
            int row = i >> 4, c4 = i & 15;
            *((float4*)&KC[row*68 + c4*4]) = ((const float4*)Kt)[i];
        }
        __syncthreads();

        // Row prefactors h(k) = exp(-0.5*||k||^2) / sqrt(M)
        if (t < TS) {
            float s = 0.f;
#pragma unroll
            for (int d = 0; d < D_; ++d) { float x = KC[t*68 + d]; s += x*x; }
            hrow[t] = __expf(-0.5f*s) * 0.125f;
        }
        __syncthreads();

        // GEMM1: proj[r][m] = sum_d K[r][d] * Om[d][m], 8 rows x 4 cols / thread
        float a1[8][4];
#pragma unroll
        for (int ir = 0; ir < 8; ++ir)
#pragma unroll
            for (int jm = 0; jm < 4; ++jm) a1[ir][jm] = 0.f;

#pragma unroll 4
        for (int d = 0; d < D_; ++d) {
            float4 bv = *((float4*)&Om[d*64 + 4*tx]);
#pragma unroll
            for (int ir = 0; ir < 8; ++ir) {
                float a = KC[(ty + 16*ir)*68 + d];
                a1[ir][0] += a*bv.x; a1[ir][1] += a*bv.y;
                a1[ir][2] += a*bv.z; a1[ir][3] += a*bv.w;
            }
        }
        // k' = h * exp(proj)  -> KP
#pragma unroll
        for (int ir = 0; ir < 8; ++ir) {
            int r = ty + 16*ir;
            float h = hrow[r];
            float4 w;
            w.x = h*__expf(a1[ir][0]); w.y = h*__expf(a1[ir][1]);
            w.z = h*__expf(a1[ir][2]); w.w = h*__expf(a1[ir][3]);
            *((float4*)&KP[r*68 + 4*tx]) = w;
        }
        __syncthreads();  // KP written; KC fully consumed -> safe to overwrite

        // Load V tile into KC
        for (int i = t; i < TS*D_/4; i += 256) {
            int row = i >> 4, c4 = i & 15;
            *((float4*)&KC[row*68 + c4*4]) = ((const float4*)Vt)[i];
        }
        __syncthreads();

        // GEMM2: acc2[im][jc] += sum_row k'[row][4*ty+im] * V[row][4*tx+jc]
        //        accD[im]     += sum_row k'[row][4*ty+im]      (ones column)
#pragma unroll 4
        for (int row = 0; row < TS; ++row) {
            float4 kv = *((float4*)&KP[row*68 + 4*ty]);
            float4 cv = *((float4*)&KC[row*68 + 4*tx]);
            float kvv[4] = {kv.x, kv.y, kv.z, kv.w};
            float cvv[4] = {cv.x, cv.y, cv.z, cv.w};
#pragma unroll
            for (int im = 0; im < 4; ++im)
#pragma unroll
                for (int jc = 0; jc < 4; ++jc)
                    acc2[im][jc] += kvv[im]*cvv[jc];
            if (tx == 15) {
#pragma unroll
                for (int im = 0; im < 4; ++im) accD[im] += kvv[im];
            }
        }
    }

    // Fold into global buf1
    float* b1 = g_buf1 + (size_t)bh*(M_*C_);
#pragma unroll
    for (int im = 0; im < 4; ++im) {
        int m = 4*ty + im;
#pragma unroll
        for (int jc = 0; jc < 4; ++jc)
            atomicAdd(&b1[m*C_ + 4*tx + jc], acc2[im][jc]);
        if (tx == 15)
            atomicAdd(&b1[m*C_ + 64], accD[im]);
    }
}

// ---------------------------------------------------------------------------
// Phase Q: q' = h(q) * exp(Q . Omega); buf2 = q' . buf1; out = num/den.
// Grid: (64 heads, 64 tiles of 128 rows). One tile per block.
// ---------------------------------------------------------------------------
__global__ void __launch_bounds__(256, 2)
phase_q_kernel(const float* __restrict__ Qg, float* __restrict__ Out,
               const float* __restrict__ Og)
{
    extern __shared__ float sm[];
    float* Om   = sm;                  // [64][64]
    float* QC   = sm + 4096;           // [128][68]  Q tile
    float* QP   = QC + TS*68;          // [128][65]  q' tile (stride 65: conflict-free col reads)
    float* B1   = QP + TS*65;          // [64][68]   buf1 (padded)
    float* hrow = B1 + 64*68;          // [128]

    const int t    = threadIdx.x;
    const int bh   = blockIdx.x;
    const int tile = blockIdx.y;
    const int tx = t & 15, ty = t >> 4;

    for (int i = t; i < (D_*M_)/4; i += 256)
        ((float4*)Om)[i] = ((const float4*)Og)[i];

    // buf1 -> smem (pad stride 65 -> 68)
    const float* b1g = g_buf1 + (size_t)bh*(M_*C_);
    for (int i = t; i < M_*C_; i += 256) {
        int m = i / C_, c = i - m*C_;
        B1[m*68 + c] = b1g[i];
    }

    const float* Qt = Qg + (size_t)bh*S_*D_ + (size_t)tile*TS*D_;
    for (int i = t; i < TS*D_/4; i += 256) {
        int row = i >> 4, c4 = i & 15;
        *((float4*)&QC[row*68 + c4*4]) = ((const float4*)Qt)[i];
    }
    __syncthreads();

    if (t < TS) {
        float s = 0.f;
#pragma unroll
        for (int d = 0; d < D_; ++d) { float x = QC[t*68 + d]; s += x*x; }
        hrow[t] = __expf(-0.5f*s) * 0.125f;
    }
    __syncthreads();

    // GEMM1: q' features
    float a1[8][4];
#pragma unroll
    for (int ir = 0; ir < 8; ++ir)
#pragma unroll
        for (int jm = 0; jm < 4; ++jm) a1[ir][jm] = 0.f;

#pragma unroll 4
    for (int d = 0; d < D_; ++d) {
        float4 bv = *((float4*)&Om[d*64 + 4*tx]);
#pragma unroll
        for (int ir = 0; ir < 8; ++ir) {
            float a = QC[(ty + 16*ir)*68 + d];
            a1[ir][0] += a*bv.x; a1[ir][1] += a*bv.y;
            a1[ir][2] += a*bv.z; a1[ir][3] += a*bv.w;
        }
    }
#pragma unroll
    for (int ir = 0; ir < 8; ++ir) {
        int r = ty + 16*ir;
        float h = hrow[r];
        QP[r*65 + 4*tx + 0] = h*__expf(a1[ir][0]);
        QP[r*65 + 4*tx + 1] = h*__expf(a1[ir][1]);
        QP[r*65 + 4*tx + 2] = h*__expf(a1[ir][2]);
        QP[r*65 + 4*tx + 3] = h*__expf(a1[ir][3]);
    }
    __syncthreads();

    // GEMM2: out[r][c] = (sum_m q'[r][m]*B1[m][c]) / (sum_m q'[r][m]*B1[m][64])
    // Thread: 4 rows x 8 cols + private denominator.
    const int rgrp = t >> 3;   // 0..31
    const int cgrp = t & 7;    // 0..7
    float acc[4][8];
    float den[4];
#pragma unroll
    for (int i = 0; i < 4; ++i) {
        den[i] = 0.f;
#pragma unroll
        for (int j = 0; j < 8; ++j) acc[i][j] = 0.f;
    }

#pragma unroll 2
    for (int m = 0; m < M_; ++m) {
        float av[4];
#pragma unroll
        for (int i = 0; i < 4; ++i) av[i] = QP[(rgrp*4 + i)*65 + m];
        float4 b0 = *((float4*)&B1[m*68 + cgrp*8]);
        float4 b1v = *((float4*)&B1[m*68 + cgrp*8 + 4]);
        float bd = B1[m*68 + 64];
        float bv[8] = {b0.x, b0.y, b0.z, b0.w, b1v.x, b1v.y, b1v.z, b1v.w};
#pragma unroll
        for (int i = 0; i < 4; ++i) {
#pragma unroll
            for (int j = 0; j < 8; ++j) acc[i][j] += av[i]*bv[j];
            den[i] += av[i]*bd;
        }
    }

    const size_t obase = ((size_t)bh*S_ + (size_t)tile*TS)*D_;
#pragma unroll
    for (int i = 0; i < 4; ++i) {
        int r = rgrp*4 + i;
        float inv = 1.0f / den[i];
        float4 o0, o1;
        o0.x = acc[i][0]*inv; o0.y = acc[i][1]*inv;
        o0.z = acc[i][2]*inv; o0.w = acc[i][3]*inv;
        o1.x = acc[i][4]*inv; o1.y = acc[i][5]*inv;
        o1.z = acc[i][6]*inv; o1.w = acc[i][7]*inv;
        *((float4*)&Out[obase + (size_t)r*D_ + cgrp*8    ]) = o0;
        *((float4*)&Out[obase + (size_t)r*D_ + cgrp*8 + 4]) = o1;
    }
}

extern "C" void kernel_launch(void* const* d_in, const int* in_sizes, int n_in,
                              void* d_out, int out_size)
{
    const float* Q  = (const float*)d_in[0];
    const float* K  = (const float*)d_in[1];
    const float* V  = (const float*)d_in[2];
    const float* Om = (const float*)d_in[3];
    float* out = (float*)d_out;
    (void)in_sizes; (void)n_in; (void)out_size;

    const int SMEM_K = (4096 + TS*68*2 + TS) * (int)sizeof(float);             // 86528 B
    const int SMEM_Q = (4096 + TS*68 + TS*65 + 64*68 + TS) * (int)sizeof(float); // 102400 B

    cudaFuncSetAttribute(phase_k_kernel, cudaFuncAttributeMaxDynamicSharedMemorySize, SMEM_K);
    cudaFuncSetAttribute(phase_q_kernel, cudaFuncAttributeMaxDynamicSharedMemorySize, SMEM_Q);

    zero_buf1_kernel<<<(BH_*M_*C_ + 255)/256, 256>>>();
    phase_k_kernel<<<dim3(BH_, NSPLIT), 256, SMEM_K>>>(K, V, Om);
    phase_q_kernel<<<dim3(BH_, S_/TS), 256, SMEM_Q>>>(Q, out, Om);
}

// round 5
// speedup vs baseline: 1.8635x; 1.8635x over previous
#include <cuda_runtime.h>

// Fixed shapes
#define BH_ 64
#define S_  8192
#define D_  64
#define M_  64
#define C_  65
#define TS  128

__device__ float g_buf1[BH_*M_*C_];

__global__ void zero_buf1_kernel() {
    int i = blockIdx.x*blockDim.x + threadIdx.x;
    if (i < BH_*M_*C_) g_buf1[i] = 0.0f;
}

__device__ __forceinline__ unsigned f2tf(float x) {   // fp32 -> tf32 (RN)
    unsigned r; asm("cvt.rna.tf32.f32 %0, %1;" : "=r"(r) : "f"(x)); return r;
}

// m16n8k8 tf32 MMA, D += A*B (fp32 accum)
__device__ __forceinline__ void mma8(float* c, const unsigned* a, const unsigned* b) {
    asm volatile("mma.sync.aligned.m16n8k8.row.col.f32.tf32.tf32.f32 "
        "{%0,%1,%2,%3}, {%4,%5,%6,%7}, {%8,%9}, {%0,%1,%2,%3};"
        : "+f"(c[0]), "+f"(c[1]), "+f"(c[2]), "+f"(c[3])
        : "r"(a[0]), "r"(a[1]), "r"(a[2]), "r"(a[3]), "r"(b[0]), "r"(b[1]));
}

// Strides (words)
#define STR_X  76   // X tile (K/V/Q), cols 0..71 used
#define STR_O  72   // Omega / B1
#define STR_P  68   // feature tile (k'/q')

// ---------------------------------------------------------------------------
// GEMM1 + exp: sOut[s][m] = f2tf( h[s] * exp( sum_d sX[s][d]*sOM[d][m] ) )
// 4 warps, warp w handles rows 32w..32w+31 (2 m16 blocks) x 64 cols.
// ---------------------------------------------------------------------------
__device__ __forceinline__ void gemm1_feature(const unsigned* sOM, const unsigned* sX,
                                              const float* hr, unsigned* sOut,
                                              int warp, int lane)
{
    float c[2][8][4];
#pragma unroll
    for (int mb = 0; mb < 2; ++mb)
#pragma unroll
        for (int nb = 0; nb < 8; ++nb)
#pragma unroll
            for (int q = 0; q < 4; ++q) c[mb][nb][q] = 0.f;

    const int lq = lane >> 2, lr = lane & 3;
#pragma unroll
    for (int k0 = 0; k0 < 8; ++k0) {
        const int kk = k0*8 + lr;
        unsigned a[2][4];
#pragma unroll
        for (int mb = 0; mb < 2; ++mb) {
            int row = warp*32 + mb*16 + lq;
            a[mb][0] = sX[row*STR_X + kk];
            a[mb][1] = sX[(row+8)*STR_X + kk];
            a[mb][2] = sX[row*STR_X + kk + 4];
            a[mb][3] = sX[(row+8)*STR_X + kk + 4];
        }
#pragma unroll
        for (int nb = 0; nb < 8; ++nb) {
            unsigned b[2];
            int col = nb*8 + lq;
            b[0] = sOM[kk*STR_O + col];
            b[1] = sOM[(kk+4)*STR_O + col];
            mma8(c[0][nb], a[0], b);
            mma8(c[1][nb], a[1], b);
        }
    }
#pragma unroll
    for (int mb = 0; mb < 2; ++mb) {
        int row = warp*32 + mb*16 + lq;
        float h0 = hr[row], h8 = hr[row+8];
#pragma unroll
        for (int nb = 0; nb < 8; ++nb) {
            int col = nb*8 + 2*lr;
            sOut[row*STR_P + col]       = f2tf(h0 * __expf(c[mb][nb][0]));
            sOut[row*STR_P + col + 1]   = f2tf(h0 * __expf(c[mb][nb][1]));
            sOut[(row+8)*STR_P + col]   = f2tf(h8 * __expf(c[mb][nb][2]));
            sOut[(row+8)*STR_P + col+1] = f2tf(h8 * __expf(c[mb][nb][3]));
        }
    }
}

// Smem word offsets
#define OFS_OM  0u
#define OFS_X   (OFS_OM + 64*STR_O)          // 4608
#define OFS_P   (OFS_X + 128*STR_X)          // X tile 9728 words
#define OFS_B1  (OFS_P + 128*STR_P)          // phase Q only
#define OFS_HRK (OFS_P + 128*STR_P)          // phase K: hrow after P
#define OFS_HRQ (OFS_B1 + 64*STR_O)          // phase Q: hrow after B1
#define PK_WORDS (OFS_HRK + 128)
#define PQ_WORDS (OFS_HRQ + 128)

// ---------------------------------------------------------------------------
// Phase K: grid (64 heads, 8 splits), 128 threads, 8 tiles per CTA.
// ---------------------------------------------------------------------------
__global__ void __launch_bounds__(128)
pk_kernel(const float* __restrict__ Kg, const float* __restrict__ Vg,
          const float* __restrict__ Og)
{
    extern __shared__ unsigned sm[];
    unsigned* sOM = sm + OFS_OM;
    unsigned* sX  = sm + OFS_X;
    unsigned* sP  = sm + OFS_P;
    float*    hr  = (float*)(sm + OFS_HRK);

    const int tid = threadIdx.x, warp = tid >> 5, lane = tid & 31;
    const int lq = lane >> 2, lr = lane & 3;
    const int bh = blockIdx.x, sp = blockIdx.y;

    // Omega [d][m] -> sOM (tf32)
    for (int i = tid; i < D_*M_; i += 128) {
        int d = i >> 6, m = i & 63;
        sOM[d*STR_O + m] = f2tf(Og[i]);
    }
    // X tile cols 64..71: ones column at 64 (for [V|1|0]), zeros beyond
    for (int i = tid; i < 128*8; i += 128) {
        int r = i >> 3, c = 64 + (i & 7);
        sX[r*STR_X + c] = (c == 64) ? 0x3f800000u : 0u;
    }

    float acc[9][4];
#pragma unroll
    for (int nb = 0; nb < 9; ++nb)
#pragma unroll
        for (int q = 0; q < 4; ++q) acc[nb][q] = 0.f;

    __syncthreads();

    for (int t = 0; t < 8; ++t) {
        const size_t rowoff = ((size_t)bh*S_ + (size_t)(sp*8 + t)*TS + tid) * D_;

        // Load K row tid, sumsq, write tf32
        {
            const float4* Kt = (const float4*)(Kg + rowoff);
            float ss = 0.f;
#pragma unroll
            for (int j = 0; j < 16; ++j) {
                float4 x = Kt[j];
                ss += x.x*x.x + x.y*x.y + x.z*x.z + x.w*x.w;
                sX[tid*STR_X + 4*j + 0] = f2tf(x.x);
                sX[tid*STR_X + 4*j + 1] = f2tf(x.y);
                sX[tid*STR_X + 4*j + 2] = f2tf(x.z);
                sX[tid*STR_X + 4*j + 3] = f2tf(x.w);
            }
            hr[tid] = __expf(-0.5f*ss) * 0.125f;
        }
        __syncthreads();

        // GEMM1 + exp -> k' in sP
        gemm1_feature(sOM, sX, hr, sP, warp, lane);
        __syncthreads();

        // Load V into sX cols 0..63
        {
            const float4* Vt = (const float4*)(Vg + rowoff);
#pragma unroll
            for (int j = 0; j < 16; ++j) {
                float4 x = Vt[j];
                sX[tid*STR_X + 4*j + 0] = f2tf(x.x);
                sX[tid*STR_X + 4*j + 1] = f2tf(x.y);
                sX[tid*STR_X + 4*j + 2] = f2tf(x.z);
                sX[tid*STR_X + 4*j + 3] = f2tf(x.w);
            }
        }
        __syncthreads();

        // GEMM2: acc[m 16w.., c] += sum_s k'[s][m] * C[s][c]; A = k'^T via sP reads
        const int m = warp*16 + lq;
#pragma unroll
        for (int k0 = 0; k0 < 16; ++k0) {
            const int kk = k0*8 + lr;
            unsigned a[4];
            a[0] = sP[kk*STR_P + m];
            a[1] = sP[kk*STR_P + m + 8];
            a[2] = sP[(kk+4)*STR_P + m];
            a[3] = sP[(kk+4)*STR_P + m + 8];
#pragma unroll
            for (int nb = 0; nb < 9; ++nb) {
                unsigned b[2];
                int col = nb*8 + lq;
                b[0] = sX[kk*STR_X + col];
                b[1] = sX[(kk+4)*STR_X + col];
                mma8(acc[nb], a, b);
            }
        }
        __syncthreads();   // sP/sX reused next tile
    }

    // Fold into global buf1
    float* b1 = g_buf1 + (size_t)bh*(M_*C_);
    const int m = warp*16 + lq;
#pragma unroll
    for (int nb = 0; nb < 9; ++nb) {
        int col = nb*8 + 2*lr;
        if (col < C_) {
            atomicAdd(&b1[m*C_ + col],     acc[nb][0]);
            atomicAdd(&b1[(m+8)*C_ + col], acc[nb][2]);
        }
        if (col + 1 < C_) {
            atomicAdd(&b1[m*C_ + col + 1],     acc[nb][1]);
            atomicAdd(&b1[(m+8)*C_ + col + 1], acc[nb][3]);
        }
    }
}

// ---------------------------------------------------------------------------
// Phase Q: grid (64 heads, 8 groups), 128 threads, 8 tiles per CTA.
// ---------------------------------------------------------------------------
__global__ void __launch_bounds__(128)
pq_kernel(const float* __restrict__ Qg, float* __restrict__ Out,
          const float* __restrict__ Og)
{
    extern __shared__ unsigned sm[];
    unsigned* sOM = sm + OFS_OM;
    unsigned* sX  = sm + OFS_X;
    unsigned* sP  = sm + OFS_P;
    unsigned* sB1 = sm + OFS_B1;
    float*    hr  = (float*)(sm + OFS_HRQ);
    float*    sXf = (float*)sX;              // staging reuse

    const int tid = threadIdx.x, warp = tid >> 5, lane = tid & 31;
    const int lq = lane >> 2, lr = lane & 3;
    const int bh = blockIdx.x, sp = blockIdx.y;

    for (int i = tid; i < D_*M_; i += 128) {
        int d = i >> 6, m = i & 63;
        sOM[d*STR_O + m] = f2tf(Og[i]);
    }
    // buf1 [m][c] -> sB1 (tf32), cols 65..71 zero
    const float* b1g = g_buf1 + (size_t)bh*(M_*C_);
    for (int i = tid; i < M_*STR_O; i += 128) {
        int m = i / STR_O, c = i - m*STR_O;
        sB1[m*STR_O + c] = (c < C_) ? f2tf(b1g[m*C_ + c]) : 0u;
    }
    __syncthreads();

    for (int t = 0; t < 8; ++t) {
        const int tt = sp*8 + t;
        const size_t rowoff = ((size_t)bh*S_ + (size_t)tt*TS + tid) * D_;

        // Load Q row tid
        {
            const float4* Qt = (const float4*)(Qg + rowoff);
            float ss = 0.f;
#pragma unroll
            for (int j = 0; j < 16; ++j) {
                float4 x = Qt[j];
                ss += x.x*x.x + x.y*x.y + x.z*x.z + x.w*x.w;
                sX[tid*STR_X + 4*j + 0] = f2tf(x.x);
                sX[tid*STR_X + 4*j + 1] = f2tf(x.y);
                sX[tid*STR_X + 4*j + 2] = f2tf(x.z);
                sX[tid*STR_X + 4*j + 3] = f2tf(x.w);
            }
            hr[tid] = __expf(-0.5f*ss) * 0.125f;
        }
        __syncthreads();

        gemm1_feature(sOM, sX, hr, sP, warp, lane);
        __syncthreads();

        // GEMM3: D[128,72] = q' (sP) @ buf1 (sB1); warp rows 32w..+31
        float d[2][9][4];
#pragma unroll
        for (int mb = 0; mb < 2; ++mb)
#pragma unroll
            for (int nb = 0; nb < 9; ++nb)
#pragma unroll
                for (int q = 0; q < 4; ++q) d[mb][nb][q] = 0.f;

#pragma unroll
        for (int k0 = 0; k0 < 8; ++k0) {
            const int kk = k0*8 + lr;
            unsigned a[2][4];
#pragma unroll
            for (int mb = 0; mb < 2; ++mb) {
                int row = warp*32 + mb*16 + lq;
                a[mb][0] = sP[row*STR_P + kk];
                a[mb][1] = sP[(row+8)*STR_P + kk];
                a[mb][2] = sP[row*STR_P + kk + 4];
                a[mb][3] = sP[(row+8)*STR_P + kk + 4];
            }
#pragma unroll
            for (int nb = 0; nb < 9; ++nb) {
                unsigned b[2];
                int col = nb*8 + lq;
                b[0] = sB1[kk*STR_O + col];
                b[1] = sB1[(kk+4)*STR_O + col];
                mma8(d[0][nb], a[0], b);
                mma8(d[1][nb], a[1], b);
            }
        }

        // Divide by denominator (col 64 = nb 8, sub-col 0) and stage into sXf
#pragma unroll
        for (int mb = 0; mb < 2; ++mb) {
            int row = warp*32 + mb*16 + lq;
            float den0 = __shfl_sync(0xffffffffu, d[mb][8][0], lane & 28);
            float den8 = __shfl_sync(0xffffffffu, d[mb][8][2], lane & 28);
            float inv0 = 1.0f / den0, inv8 = 1.0f / den8;
#pragma unroll
            for (int nb = 0; nb < 8; ++nb) {
                int col = nb*8 + 2*lr;
                sXf[row*STR_X + col]       = d[mb][nb][0]*inv0;
                sXf[row*STR_X + col + 1]   = d[mb][nb][1]*inv0;
                sXf[(row+8)*STR_X + col]   = d[mb][nb][2]*inv8;
                sXf[(row+8)*STR_X + col+1] = d[mb][nb][3]*inv8;
            }
        }
        __syncthreads();

        // Coalesced store: 128 rows x 64 cols
        float* ob = Out + ((size_t)bh*S_ + (size_t)tt*TS)*D_;
        for (int i = tid; i < 2048; i += 128) {
            int r = i >> 4, c4 = i & 15;
            float4 w = *(float4*)&sXf[r*STR_X + 4*c4];
            ((float4*)(ob + (size_t)r*D_))[c4] = w;
        }
        __syncthreads();   // sX reused next tile
    }
}

extern "C" void kernel_launch(void* const* d_in, const int* in_sizes, int n_in,
                              void* d_out, int out_size)
{
    const float* Q  = (const float*)d_in[0];
    const float* K  = (const float*)d_in[1];
    const float* V  = (const float*)d_in[2];
    const float* Om = (const float*)d_in[3];
    float* out = (float*)d_out;
    (void)in_sizes; (void)n_in; (void)out_size;

    const int SMEM_K = PK_WORDS * 4;
    const int SMEM_Q = PQ_WORDS * 4;
    cudaFuncSetAttribute(pk_kernel, cudaFuncAttributeMaxDynamicSharedMemorySize, SMEM_K);
    cudaFuncSetAttribute(pq_kernel, cudaFuncAttributeMaxDynamicSharedMemorySize, SMEM_Q);

    zero_buf1_kernel<<<(BH_*M_*C_ + 255)/256, 256>>>();
    pk_kernel<<<dim3(BH_, 8), 128, SMEM_K>>>(K, V, Om);
    pq_kernel<<<dim3(BH_, 8), 128, SMEM_Q>>>(Q, out, Om);
}

// round 6
// speedup vs baseline: 1.9774x; 1.0611x over previous
#include <cuda_runtime.h>

// Fixed shapes
#define BH_ 64
#define S_  8192
#define D_  64
#define M_  64
#define C_  65
#define TS  128
#define NT  8      // tiles per CTA

__device__ float g_buf1[BH_*M_*C_];

__global__ void zero_buf1_kernel() {
    int i = blockIdx.x*blockDim.x + threadIdx.x;
    if (i < BH_*M_*C_) g_buf1[i] = 0.0f;
}

__device__ __forceinline__ unsigned f2tf(float x) {   // fp32 -> tf32 (RN)
    unsigned r; asm("cvt.rna.tf32.f32 %0, %1;" : "=r"(r) : "f"(x)); return r;
}
__device__ __forceinline__ unsigned smem_u32(const void* p) {
    unsigned a;
    asm("{ .reg .u64 t; cvta.to.shared.u64 t, %1; cvt.u32.u64 %0, t; }" : "=r"(a) : "l"(p));
    return a;
}
__device__ __forceinline__ void cp16(unsigned saddr, const float* g) {
    asm volatile("cp.async.cg.shared.global [%0], [%1], 16;"
                 :: "r"(saddr), "l"(__cvta_generic_to_global(g)));
}
#define CP_COMMIT() asm volatile("cp.async.commit_group;")
#define CP_WAIT1()  asm volatile("cp.async.wait_group 1;")
#define CP_WAIT0()  asm volatile("cp.async.wait_group 0;")

// m16n8k8 tf32 MMA, D += A*B (fp32 accum)
__device__ __forceinline__ void mma8(float* c, const unsigned* a, const unsigned* b) {
    asm volatile("mma.sync.aligned.m16n8k8.row.col.f32.tf32.tf32.f32 "
        "{%0,%1,%2,%3}, {%4,%5,%6,%7}, {%8,%9}, {%0,%1,%2,%3};"
        : "+f"(c[0]), "+f"(c[1]), "+f"(c[2]), "+f"(c[3])
        : "r"(a[0]), "r"(a[1]), "r"(a[2]), "r"(a[3]), "r"(b[0]), "r"(b[1]));
}

// Strides (words)
#define STR_X  76   // raw fp32 X tiles (K/V/Q), cols 0..71 used
#define STR_O  72   // Omega / B1 (tf32)
#define STR_P  68   // feature tile k'/q' (tf32)

// Word offsets, phase K
#define KOF_OM  0u
#define KOF_X0  4608u
#define KOF_X1  (KOF_X0 + 128u*STR_X)     // 14336
#define KOF_V0  (KOF_X1 + 128u*STR_X)     // 24064
#define KOF_V1  (KOF_V0 + 128u*STR_X)     // 33792
#define KOF_P   (KOF_V1 + 128u*STR_X)     // 43520
#define KOF_HR  (KOF_P  + 128u*STR_P)     // 52224
#define PK_WORDS (KOF_HR + 128u)          // 52352 -> 209408 B

// Word offsets, phase Q
#define QOF_OM  0u
#define QOF_X0  4608u
#define QOF_X1  (QOF_X0 + 128u*STR_X)     // 14336
#define QOF_P   (QOF_X1 + 128u*STR_X)     // 24064
#define QOF_B1  (QOF_P  + 128u*STR_P)     // 32768
#define QOF_HR  (QOF_B1 + 64u*STR_O)      // 37376
#define PQ_WORDS (QOF_HR + 128u)          // 37504 -> 150016 B

// Issue one 128x64 fp32 tile as 16 cp.async/thread (coalesced)
__device__ __forceinline__ void issue_tile(const float* g, unsigned sbase, int tid) {
#pragma unroll
    for (int j = 0; j < 16; ++j) {
        int l = j*128 + tid;          // 0..2047 16B-chunks
        int row = l >> 4, ch = l & 15;
        cp16(sbase + (unsigned)(row*STR_X + ch*4)*4u, g + row*64 + ch*4);
    }
}

// GEMM1 + exp: sOut[s][m] = tf32( h[s] * exp( sum_d sX[s][d]*sOM[d][m] ) )
// 4 warps; warp w: rows 32w..32w+31 (2 m16 blocks) x 64 cols. sX is raw fp32.
__device__ __forceinline__ void gemm1_feature(const unsigned* sOM, const float* sX,
                                              const float* hr, unsigned* sOut,
                                              int warp, int lane)
{
    float c[2][8][4];
#pragma unroll
    for (int mb = 0; mb < 2; ++mb)
#pragma unroll
        for (int nb = 0; nb < 8; ++nb)
#pragma unroll
            for (int q = 0; q < 4; ++q) c[mb][nb][q] = 0.f;

    const int lq = lane >> 2, lr = lane & 3;
#pragma unroll
    for (int k0 = 0; k0 < 8; ++k0) {
        const int kk = k0*8 + lr;
        unsigned a[2][4];
#pragma unroll
        for (int mb = 0; mb < 2; ++mb) {
            int row = warp*32 + mb*16 + lq;
            a[mb][0] = f2tf(sX[row*STR_X + kk]);
            a[mb][1] = f2tf(sX[(row+8)*STR_X + kk]);
            a[mb][2] = f2tf(sX[row*STR_X + kk + 4]);
            a[mb][3] = f2tf(sX[(row+8)*STR_X + kk + 4]);
        }
#pragma unroll
        for (int nb = 0; nb < 8; ++nb) {
            unsigned b[2];
            int col = nb*8 + lq;
            b[0] = sOM[kk*STR_O + col];
            b[1] = sOM[(kk+4)*STR_O + col];
            mma8(c[0][nb], a[0], b);
            mma8(c[1][nb], a[1], b);
        }
    }
#pragma unroll
    for (int mb = 0; mb < 2; ++mb) {
        int row = warp*32 + mb*16 + lq;
        float h0 = hr[row], h8 = hr[row+8];
#pragma unroll
        for (int nb = 0; nb < 8; ++nb) {
            int col = nb*8 + 2*lr;
            sOut[row*STR_P + col]       = f2tf(h0 * __expf(c[mb][nb][0]));
            sOut[row*STR_P + col + 1]   = f2tf(h0 * __expf(c[mb][nb][1]));
            sOut[(row+8)*STR_P + col]   = f2tf(h8 * __expf(c[mb][nb][2]));
            sOut[(row+8)*STR_P + col+1] = f2tf(h8 * __expf(c[mb][nb][3]));
        }
    }
}

// ---------------------------------------------------------------------------
// Phase K: grid (64 heads, 8 splits), 128 threads, NT tiles, cp.async pipeline
// ---------------------------------------------------------------------------
__global__ void __launch_bounds__(128)
pk_kernel(const float* __restrict__ Kg, const float* __restrict__ Vg,
          const float* __restrict__ Og)
{
    extern __shared__ unsigned sm[];
    unsigned* sOM = sm + KOF_OM;
    float*    sXf[2] = { (float*)(sm + KOF_X0), (float*)(sm + KOF_X1) };
    float*    sVf[2] = { (float*)(sm + KOF_V0), (float*)(sm + KOF_V1) };
    unsigned* sP  = sm + KOF_P;
    float*    hr  = (float*)(sm + KOF_HR);
    const unsigned xb[2] = { smem_u32(sm + KOF_X0), smem_u32(sm + KOF_X1) };
    const unsigned vb[2] = { smem_u32(sm + KOF_V0), smem_u32(sm + KOF_V1) };

    const int tid = threadIdx.x, warp = tid >> 5, lane = tid & 31;
    const int lq = lane >> 2, lr = lane & 3;
    const int bh = blockIdx.x, sp = blockIdx.y;

    // Omega [d][m] -> sOM (tf32)
    for (int i = tid; i < D_*M_; i += 128) {
        int d = i >> 6, m = i & 63;
        sOM[d*STR_O + m] = f2tf(Og[i]);
    }
    // V tiles: cols 64..71 constant [1|0...] for both buffers
    for (int i = tid; i < 128*8; i += 128) {
        int r = i >> 3, c = 64 + (i & 7);
        float v = (c == 64) ? 1.0f : 0.0f;
        sVf[0][r*STR_X + c] = v;
        sVf[1][r*STR_X + c] = v;
    }

    float acc[9][4];
#pragma unroll
    for (int nb = 0; nb < 9; ++nb)
#pragma unroll
        for (int q = 0; q < 4; ++q) acc[nb][q] = 0.f;

    const size_t base0 = ((size_t)bh*S_ + (size_t)(sp*NT)*TS) * D_;
    issue_tile(Kg + base0, xb[0], tid);
    issue_tile(Vg + base0, vb[0], tid);
    CP_COMMIT();

    for (int t = 0; t < NT; ++t) {
        const int b = t & 1;
        if (t + 1 < NT) {
            const size_t nb_off = base0 + (size_t)(t+1)*TS*D_;
            issue_tile(Kg + nb_off, xb[b^1], tid);
            issue_tile(Vg + nb_off, vb[b^1], tid);
            CP_COMMIT();
            CP_WAIT1();
        } else {
            CP_WAIT0();
        }
        __syncthreads();

        // row prefactors from smem
        {
            const float4* rp = (const float4*)(sXf[b] + tid*STR_X);
            float ss = 0.f;
#pragma unroll
            for (int j = 0; j < 16; ++j) {
                float4 x = rp[j];
                ss += x.x*x.x + x.y*x.y + x.z*x.z + x.w*x.w;
            }
            hr[tid] = __expf(-0.5f*ss) * 0.125f;
        }
        __syncthreads();

        gemm1_feature(sOM, sXf[b], hr, sP, warp, lane);
        __syncthreads();

        // GEMM2: acc[m,c] += sum_s k'[s][m] * C[s][c]
        const int m = warp*16 + lq;
        const float* sV = sVf[b];
#pragma unroll
        for (int k0 = 0; k0 < 16; ++k0) {
            const int kk = k0*8 + lr;
            unsigned a[4];
            a[0] = sP[kk*STR_P + m];
            a[1] = sP[kk*STR_P + m + 8];
            a[2] = sP[(kk+4)*STR_P + m];
            a[3] = sP[(kk+4)*STR_P + m + 8];
#pragma unroll
            for (int nb = 0; nb < 9; ++nb) {
                unsigned bfr[2];
                int col = nb*8 + lq;
                bfr[0] = f2tf(sV[kk*STR_X + col]);
                bfr[1] = f2tf(sV[(kk+4)*STR_X + col]);
                mma8(acc[nb], a, bfr);
            }
        }
        __syncthreads();   // sP reused next tile
    }

    // Fold into global buf1
    float* b1 = g_buf1 + (size_t)bh*(M_*C_);
    const int m = warp*16 + lq;
#pragma unroll
    for (int nb = 0; nb < 9; ++nb) {
        int col = nb*8 + 2*lr;
        if (col < C_) {
            atomicAdd(&b1[m*C_ + col],     acc[nb][0]);
            atomicAdd(&b1[(m+8)*C_ + col], acc[nb][2]);
        }
        if (col + 1 < C_) {
            atomicAdd(&b1[m*C_ + col + 1],     acc[nb][1]);
            atomicAdd(&b1[(m+8)*C_ + col + 1], acc[nb][3]);
        }
    }
}

// ---------------------------------------------------------------------------
// Phase Q: grid (64 heads, 8 groups), 128 threads, NT tiles, cp.async pipeline
// ---------------------------------------------------------------------------
__global__ void __launch_bounds__(128)
pq_kernel(const float* __restrict__ Qg, float* __restrict__ Out,
          const float* __restrict__ Og)
{
    extern __shared__ unsigned sm[];
    unsigned* sOM = sm + QOF_OM;
    float*    sXf[2] = { (float*)(sm + QOF_X0), (float*)(sm + QOF_X1) };
    unsigned* sP  = sm + QOF_P;
    unsigned* sB1 = sm + QOF_B1;
    float*    hr  = (float*)(sm + QOF_HR);
    const unsigned xb[2] = { smem_u32(sm + QOF_X0), smem_u32(sm + QOF_X1) };

    const int tid = threadIdx.x, warp = tid >> 5, lane = tid & 31;
    const int lq = lane >> 2, lr = lane & 3;
    const int bh = blockIdx.x, sp = blockIdx.y;

    for (int i = tid; i < D_*M_; i += 128) {
        int d = i >> 6, m = i & 63;
        sOM[d*STR_O + m] = f2tf(Og[i]);
    }
    const float* b1g = g_buf1 + (size_t)bh*(M_*C_);
    for (int i = tid; i < M_*STR_O; i += 128) {
        int m = i / STR_O, c = i - m*STR_O;
        sB1[m*STR_O + c] = (c < C_) ? f2tf(b1g[m*C_ + c]) : 0u;
    }

    const size_t base0 = ((size_t)bh*S_ + (size_t)(sp*NT)*TS) * D_;
    issue_tile(Qg + base0, xb[0], tid);
    CP_COMMIT();

    for (int t = 0; t < NT; ++t) {
        const int b = t & 1;
        if (t + 1 < NT) {
            issue_tile(Qg + base0 + (size_t)(t+1)*TS*D_, xb[b^1], tid);
            CP_COMMIT();
            CP_WAIT1();
        } else {
            CP_WAIT0();
        }
        __syncthreads();

        {
            const float4* rp = (const float4*)(sXf[b] + tid*STR_X);
            float ss = 0.f;
#pragma unroll
            for (int j = 0; j < 16; ++j) {
                float4 x = rp[j];
                ss += x.x*x.x + x.y*x.y + x.z*x.z + x.w*x.w;
            }
            hr[tid] = __expf(-0.5f*ss) * 0.125f;
        }
        __syncthreads();

        gemm1_feature(sOM, sXf[b], hr, sP, warp, lane);
        __syncthreads();

        // GEMM3: D[128,72] = q' (sP) @ buf1 (sB1); warp rows 32w..+31
        float d[2][9][4];
#pragma unroll
        for (int mb = 0; mb < 2; ++mb)
#pragma unroll
            for (int nb = 0; nb < 9; ++nb)
#pragma unroll
                for (int q = 0; q < 4; ++q) d[mb][nb][q] = 0.f;

#pragma unroll
        for (int k0 = 0; k0 < 8; ++k0) {
            const int kk = k0*8 + lr;
            unsigned a[2][4];
#pragma unroll
            for (int mb = 0; mb < 2; ++mb) {
                int row = warp*32 + mb*16 + lq;
                a[mb][0] = sP[row*STR_P + kk];
                a[mb][1] = sP[(row+8)*STR_P + kk];
                a[mb][2] = sP[row*STR_P + kk + 4];
                a[mb][3] = sP[(row+8)*STR_P + kk + 4];
            }
#pragma unroll
            for (int nb = 0; nb < 9; ++nb) {
                unsigned bfr[2];
                int col = nb*8 + lq;
                bfr[0] = sB1[kk*STR_O + col];
                bfr[1] = sB1[(kk+4)*STR_O + col];
                mma8(d[0][nb], a[0], bfr);
                mma8(d[1][nb], a[1], bfr);
            }
        }

        // divide by denominator, stage into free X buffer (current b)
        float* stg = sXf[b];
#pragma unroll
        for (int mb = 0; mb < 2; ++mb) {
            int row = warp*32 + mb*16 + lq;
            float den0 = __shfl_sync(0xffffffffu, d[mb][8][0], lane & 28);
            float den8 = __shfl_sync(0xffffffffu, d[mb][8][2], lane & 28);
            float inv0 = 1.0f / den0, inv8 = 1.0f / den8;
#pragma unroll
            for (int nb = 0; nb < 8; ++nb) {
                int col = nb*8 + 2*lr;
                stg[row*STR_X + col]       = d[mb][nb][0]*inv0;
                stg[row*STR_X + col + 1]   = d[mb][nb][1]*inv0;
                stg[(row+8)*STR_X + col]   = d[mb][nb][2]*inv8;
                stg[(row+8)*STR_X + col+1] = d[mb][nb][3]*inv8;
            }
        }
        __syncthreads();

        // coalesced store
        float* ob = Out + base0 + (size_t)t*TS*D_;
        for (int i = tid; i < 2048; i += 128) {
            int r = i >> 4, c4 = i & 15;
            float4 w = *(float4*)&stg[r*STR_X + 4*c4];
            ((float4*)(ob + (size_t)r*D_))[c4] = w;
        }
        __syncthreads();   // stg (= sXf[b]) reused as cp.async dst two tiles later
    }
}

extern "C" void kernel_launch(void* const* d_in, const int* in_sizes, int n_in,
                              void* d_out, int out_size)
{
    const float* Q  = (const float*)d_in[0];
    const float* K  = (const float*)d_in[1];
    const float* V  = (const float*)d_in[2];
    const float* Om = (const float*)d_in[3];
    float* out = (float*)d_out;
    (void)in_sizes; (void)n_in; (void)out_size;

    const int SMEM_K = PK_WORDS * 4;
    const int SMEM_Q = PQ_WORDS * 4;
    cudaFuncSetAttribute(pk_kernel, cudaFuncAttributeMaxDynamicSharedMemorySize, SMEM_K);
    cudaFuncSetAttribute(pq_kernel, cudaFuncAttributeMaxDynamicSharedMemorySize, SMEM_Q);

    zero_buf1_kernel<<<(BH_*M_*C_ + 255)/256, 256>>>();
    pk_kernel<<<dim3(BH_, S_/(TS*NT)), 128, SMEM_K>>>(K, V, Om);
    pq_kernel<<<dim3(BH_, S_/(TS*NT)), 128, SMEM_Q>>>(Q, out, Om);
}